// round 5
// baseline (speedup 1.0000x reference)
#include <cuda_runtime.h>
#include <cuda_bf16.h>
#include <math.h>

// ---------------- Problem constants (fixed by the dataset shapes) ------------
#define GB 7            // GROUP_SIZE
#define DB 10           // D = C / (G*G) = 490/49
#define BB 2            // batch
#define CB 490          // channels
#define HB 128          // feature H
#define WB 128          // feature W
#define HP 129          // padded H+1
#define WP 129          // padded W+1
#define NROI 512

// Integral image scratch: S[b][c][h][w], (h,w) zero-padded at 0.
// 2*490*129*129 floats = ~65.2 MB. Static device array (allocation-free).
__device__ float g_S[(size_t)BB * CB * HP * WP];

// ---------------- Kernel 1: zero the h==0 plane ------------------------------
__global__ void k_zero_top() {
    int i = blockIdx.x * blockDim.x + threadIdx.x;
    const int total = BB * CB * WP;
    if (i < total) {
        int bc = i / WP;
        int w  = i - bc * WP;
        g_S[(size_t)bc * HP * WP + w] = 0.0f;
    }
}

// ---------------- Kernel 2: row-wise inclusive prefix (W direction) ----------
// One warp per (b,c,h) row of 128 elems: 4 segments of 32, shfl scan + carry.
__global__ void k_rowscan(const float* __restrict__ feat) {
    int gwarp = (blockIdx.x * blockDim.x + threadIdx.x) >> 5;
    int lane  = threadIdx.x & 31;
    const int nrows = BB * CB * HB;
    if (gwarp >= nrows) return;
    int h  = gwarp % HB;
    int bc = gwarp / HB;
    const float* src = feat + ((size_t)bc * HB + h) * WB;
    float* dst = g_S + ((size_t)bc * HP + (h + 1)) * WP;
    if (lane == 0) dst[0] = 0.0f;   // w==0 pad column
    float carry = 0.0f;
    #pragma unroll
    for (int s = 0; s < 4; ++s) {
        float v = src[s * 32 + lane];
        #pragma unroll
        for (int o = 1; o < 32; o <<= 1) {
            float t = __shfl_up_sync(0xffffffffu, v, o);
            if (lane >= o) v += t;
        }
        v += carry;
        dst[1 + s * 32 + lane] = v;
        carry = __shfl_sync(0xffffffffu, v, 31);
    }
}

// ---------------- Kernel 3: column-wise prefix (H direction) -----------------
// One thread per (b,c,w) column; consecutive threads -> consecutive w (coalesced).
__global__ void k_colscan() {
    int i = blockIdx.x * blockDim.x + threadIdx.x;
    const int total = BB * CB * WP;
    if (i >= total) return;
    int w  = i % WP;
    int bc = i / WP;
    float* col = g_S + (size_t)bc * HP * WP + w;
    float acc = 0.0f;          // row 0 is the zero pad
    #pragma unroll 4
    for (int h = 1; h < HP; ++h) {
        acc += col[(size_t)h * WP];
        col[(size_t)h * WP] = acc;
    }
}

// ---------------- Kernel 4: PSRoI pooling from the integral image ------------
// One thread per output element (n, d, pi, pj). Bin math mirrors the reference
// op-for-op in fp32; *_rn intrinsics forbid FMA contraction so floor/ceil
// boundaries match the JAX reference bit-for-bit.
__global__ void k_pool(const float* __restrict__ rois,
                       const void*  __restrict__ stride_ptr,
                       float* __restrict__ out) {
    int idx = blockIdx.x * blockDim.x + threadIdx.x;
    const int total = NROI * DB * GB * GB;
    if (idx >= total) return;

    int pj = idx % GB;
    int t  = idx / GB;
    int pi = t % GB;  t /= GB;
    int d  = t % DB;
    int n  = t / DB;

    // stride may arrive as int32 or float32 scalar; decode from bits.
    float stride_f = 16.0f;
    if (stride_ptr) {
        int iv = *(const int*)stride_ptr;
        stride_f = (iv > 0 && iv < 100000) ? (float)iv : *(const float*)stride_ptr;
    }
    float sscale = 1.0f / stride_f;

    const float* r = rois + (size_t)n * 5;
    int b = (int)r[0];
    float rsw = __fmul_rn(rintf(r[1]), sscale);
    float rsh = __fmul_rn(rintf(r[2]), sscale);
    float rew = __fmul_rn(__fadd_rn(rintf(r[3]), 1.0f), sscale);
    float reh = __fmul_rn(__fadd_rn(rintf(r[4]), 1.0f), sscale);
    float rw  = __fsub_rn(rew, rsw);
    float rh  = __fsub_rn(reh, rsh);
    float rwm = __fmul_rn(rw, 1.3f);
    float rhm = __fmul_rn(rh, 1.3f);
    float swm = __fsub_rn(__fmul_rn(__fadd_rn(rsw, rew), 0.5f), __fmul_rn(rwm, 0.5f));
    float shm = __fsub_rn(__fmul_rn(__fadd_rn(rsh, reh), 0.5f), __fmul_rn(rhm, 0.5f));
    rwm = fmaxf(rwm, 0.1f);
    rhm = fmaxf(rhm, 0.1f);
    float bin_h = __fdiv_rn(rhm, 7.0f);
    float bin_w = __fdiv_rn(rwm, 7.0f);
    float dh = __fmul_rn(__fmul_rn(bin_h, 0.5f), 0.5f);  // bin_h*(1.5-1)*0.5
    float dw = __fmul_rn(__fmul_rn(bin_w, 0.5f), 0.5f);

    float gi = (float)pi, gj = (float)pj;
    float hs_f = floorf(__fsub_rn(__fadd_rn(shm, __fmul_rn(gi, bin_h)), dh));
    float he_f = ceilf (__fadd_rn(__fadd_rn(shm, __fmul_rn(__fadd_rn(gi, 1.0f), bin_h)), dh));
    float ws_f = floorf(__fsub_rn(__fadd_rn(swm, __fmul_rn(gj, bin_w)), dw));
    float we_f = ceilf (__fadd_rn(__fadd_rn(swm, __fmul_rn(__fadd_rn(gj, 1.0f), bin_w)), dw));
    int hs = (int)fminf(fmaxf(hs_f, 0.0f), 128.0f);
    int he = (int)fminf(fmaxf(he_f, 0.0f), 128.0f);
    int ws = (int)fminf(fmaxf(ws_f, 0.0f), 128.0f);
    int we = (int)fminf(fmaxf(we_f, 0.0f), 128.0f);

    int c = d * (GB * GB) + pi * GB + pj;
    const float* S = g_S + ((size_t)(b * CB + c)) * HP * WP;
    float total_v = S[(size_t)he * WP + we] - S[(size_t)hs * WP + we]
                  - S[(size_t)he * WP + ws] + S[(size_t)hs * WP + ws];
    int area = (he - hs) * (we - ws);
    out[idx] = (area > 0) ? __fdiv_rn(total_v, (float)max(area, 1)) : 0.0f;
}

// -----------------------------------------------------------------------------
extern "C" void kernel_launch(void* const* d_in, const int* in_sizes, int n_in,
                              void* d_out, int out_size) {
    // Identify inputs by element count (robust to ordering).
    const float* rois = nullptr;
    const float* feat = nullptr;
    const void*  stride_ptr = nullptr;
    for (int i = 0; i < n_in; ++i) {
        if (in_sizes[i] == NROI * 5)                  rois = (const float*)d_in[i];
        else if (in_sizes[i] == BB * CB * HB * WB)    feat = (const float*)d_in[i];
        else if (in_sizes[i] == 1)                    stride_ptr = d_in[i];
    }
    float* out = (float*)d_out;

    // 1) zero top pad plane
    {
        int total = BB * CB * WP;
        k_zero_top<<<(total + 255) / 256, 256>>>();
    }
    // 2) row scan: one warp per (b,c,h)
    {
        int nrows = BB * CB * HB;                 // 125440 warps
        long long threads = (long long)nrows * 32;
        int blocks = (int)((threads + 255) / 256);
        k_rowscan<<<blocks, 256>>>(feat);
    }
    // 3) column scan: one thread per (b,c,w)
    {
        int total = BB * CB * WP;
        k_colscan<<<(total + 255) / 256, 256>>>();
    }
    // 4) pooling
    {
        int total = NROI * DB * GB * GB;          // 250880 == out_size
        k_pool<<<(total + 255) / 256, 256>>>(rois, stride_ptr, out);
    }
}

// round 10
// speedup vs baseline: 1.8174x; 1.8174x over previous
#include <cuda_runtime.h>
#include <cuda_bf16.h>
#include <math.h>

// ---------------- Problem constants (fixed by the dataset shapes) ------------
#define GB 7            // GROUP_SIZE
#define DB 10           // D = C / (G*G) = 490/49
#define BB 2            // batch
#define CB 490          // channels
#define HB 128          // feature H
#define WB 128          // feature W
#define NROI 512

// Smem integral image: S[h][w], h,w in [0,128]; row stride 130 floats so that
// column-strided access (fixed w, varying h) is bank-conflict-free
// ((130 mod 32)=2 -> consecutive w hit consecutive banks at every h).
#define SST 130
#define SMEM_BYTES ((HB + 1) * SST * 4)   // 129*130*4 = 67080 B (dynamic smem)

// ---------------- Fully fused kernel -----------------------------------------
// One CTA per (b,c) plane. Load plane -> row scan (shfl) -> column scan (smem)
// -> pool all ROIs of batch b for this channel, straight out of smem.
// The integral image never exists in global memory.
__global__ void k_fused(const float* __restrict__ feat,
                        const float* __restrict__ rois,
                        const void*  __restrict__ stride_ptr,
                        float* __restrict__ out) {
    extern __shared__ float S[];          // [129][SST]

    const int bc   = blockIdx.x;          // 0 .. BB*CB-1
    const int b    = bc / CB;
    const int c    = bc % CB;
    const int tid  = threadIdx.x;         // 256 threads
    const int lane = tid & 31;
    const int warp = tid >> 5;            // 8 warps

    // --- zero pad row h==0 (cols 0..129) ---
    for (int w = tid; w < SST; w += blockDim.x) S[w] = 0.0f;

    // --- row-wise inclusive prefix (W direction): warp per row, 16 rows/warp ---
    const float* plane = feat + (size_t)bc * HB * WB;
    for (int h = warp; h < HB; h += 8) {
        const float* src = plane + h * WB;
        float* dst = S + (h + 1) * SST;
        if (lane == 0) dst[0] = 0.0f;     // pad column w==0
        float carry = 0.0f;
        #pragma unroll
        for (int s = 0; s < 4; ++s) {
            float v = src[s * 32 + lane];
            #pragma unroll
            for (int o = 1; o < 32; o <<= 1) {
                float t = __shfl_up_sync(0xffffffffu, v, o);
                if (lane >= o) v += t;
            }
            v += carry;
            dst[1 + s * 32 + lane] = v;
            carry = __shfl_sync(0xffffffffu, v, 31);
        }
    }
    __syncthreads();

    // --- column-wise prefix (H direction): thread per column w=1..128 ---
    if (tid < HB) {
        const int w = tid + 1;
        float acc = 0.0f;
        #pragma unroll 8
        for (int h = 1; h <= HB; ++h) {
            acc += S[h * SST + w];
            S[h * SST + w] = acc;
        }
    }
    __syncthreads();

    // --- pooling for this channel's (d,pi,pj), ROIs of batch b ---
    const int rem = c % (GB * GB);
    const int pi  = rem / GB;
    const int pj  = rem % GB;

    float stride_f = 16.0f;
    if (stride_ptr) {
        int iv = *(const int*)stride_ptr;
        stride_f = (iv > 0 && iv < 100000) ? (float)iv : *(const float*)stride_ptr;
    }
    const float sscale = 1.0f / stride_f;
    const float gi = (float)pi, gj = (float)pj;

    for (int n = tid; n < NROI; n += blockDim.x) {
        const float* r = rois + (size_t)n * 5;
        if ((int)r[0] != b) continue;

        // Bin math mirrors the reference op-for-op; *_rn intrinsics forbid FMA
        // contraction so floor/ceil boundaries match the JAX reference.
        float rsw = __fmul_rn(rintf(r[1]), sscale);
        float rsh = __fmul_rn(rintf(r[2]), sscale);
        float rew = __fmul_rn(__fadd_rn(rintf(r[3]), 1.0f), sscale);
        float reh = __fmul_rn(__fadd_rn(rintf(r[4]), 1.0f), sscale);
        float rw  = __fsub_rn(rew, rsw);
        float rh  = __fsub_rn(reh, rsh);
        float rwm = __fmul_rn(rw, 1.3f);
        float rhm = __fmul_rn(rh, 1.3f);
        float swm = __fsub_rn(__fmul_rn(__fadd_rn(rsw, rew), 0.5f), __fmul_rn(rwm, 0.5f));
        float shm = __fsub_rn(__fmul_rn(__fadd_rn(rsh, reh), 0.5f), __fmul_rn(rhm, 0.5f));
        rwm = fmaxf(rwm, 0.1f);
        rhm = fmaxf(rhm, 0.1f);
        float bin_h = __fdiv_rn(rhm, 7.0f);
        float bin_w = __fdiv_rn(rwm, 7.0f);
        float dh = __fmul_rn(__fmul_rn(bin_h, 0.5f), 0.5f);   // bin_h*(1.5-1)*0.5
        float dw = __fmul_rn(__fmul_rn(bin_w, 0.5f), 0.5f);

        float hs_f = floorf(__fsub_rn(__fadd_rn(shm, __fmul_rn(gi, bin_h)), dh));
        float he_f = ceilf (__fadd_rn(__fadd_rn(shm, __fmul_rn(__fadd_rn(gi, 1.0f), bin_h)), dh));
        float ws_f = floorf(__fsub_rn(__fadd_rn(swm, __fmul_rn(gj, bin_w)), dw));
        float we_f = ceilf (__fadd_rn(__fadd_rn(swm, __fmul_rn(__fadd_rn(gj, 1.0f), bin_w)), dw));
        int hs = (int)fminf(fmaxf(hs_f, 0.0f), 128.0f);
        int he = (int)fminf(fmaxf(he_f, 0.0f), 128.0f);
        int ws = (int)fminf(fmaxf(ws_f, 0.0f), 128.0f);
        int we = (int)fminf(fmaxf(we_f, 0.0f), 128.0f);

        float tot = S[he * SST + we] - S[hs * SST + we]
                  - S[he * SST + ws] + S[hs * SST + ws];
        int area = (he - hs) * (we - ws);
        out[(size_t)n * CB + c] = (area > 0) ? __fdiv_rn(tot, (float)max(area, 1)) : 0.0f;
    }
}

// -----------------------------------------------------------------------------
extern "C" void kernel_launch(void* const* d_in, const int* in_sizes, int n_in,
                              void* d_out, int out_size) {
    // Identify inputs by element count (robust to ordering).
    const float* rois = nullptr;
    const float* feat = nullptr;
    const void*  stride_ptr = nullptr;
    for (int i = 0; i < n_in; ++i) {
        if (in_sizes[i] == NROI * 5)                  rois = (const float*)d_in[i];
        else if (in_sizes[i] == BB * CB * HB * WB)    feat = (const float*)d_in[i];
        else if (in_sizes[i] == 1)                    stride_ptr = d_in[i];
    }
    float* out = (float*)d_out;

    // 67 KB dynamic smem > 48 KB default: opt in once per call (host-state
    // change, not a stream op -> safe under graph capture; no allocation).
    static bool attr_set = false;
    if (!attr_set) {
        cudaFuncSetAttribute(k_fused,
                             cudaFuncAttributeMaxDynamicSharedMemorySize,
                             SMEM_BYTES);
        attr_set = true;
    }

    k_fused<<<BB * CB, 256, SMEM_BYTES>>>(feat, rois, stride_ptr, out);
}

// round 11
// speedup vs baseline: 1.8330x; 1.0086x over previous
#include <cuda_runtime.h>
#include <cuda_bf16.h>
#include <math.h>

// ---------------- Problem constants (fixed by the dataset shapes) ------------
#define GB 7            // GROUP_SIZE
#define DB 10           // D = C / (G*G) = 490/49
#define BB 2            // batch
#define CB 490          // channels
#define HB 128          // feature H
#define WB 128          // feature W
#define NROI 512

// Smem integral image row stride: 129 floats. With scalar LDS/STS this makes
// the column scan (lanes = consecutive w) conflict-free and the row-scan
// stores at worst 4-way.
#define SST 129
#define SMEM_BYTES ((HB + 1) * SST * 4)   // 129*129*4 = 66564 B (dynamic smem)

// ---------------- Precomputed per-ROI bin table ------------------------------
// hs/he/ws/we are in [0,128] -> packed as (lo | hi<<8). Bin boundaries depend
// only on (n, g), NOT on the channel, so compute them once instead of 490x.
__device__ int            g_bidx[NROI];
__device__ unsigned short g_hb[NROI * GB];   // hs | (he<<8), indexed [n*7+pi]
__device__ unsigned short g_wb[NROI * GB];   // ws | (we<<8), indexed [n*7+pj]

// ---------------- Kernel 1: ROI bin precompute (512 threads total) -----------
// Bin math mirrors the reference op-for-op; *_rn intrinsics forbid FMA
// contraction so floor/ceil boundaries match the JAX reference exactly.
__global__ void k_roi(const float* __restrict__ rois,
                      const void*  __restrict__ stride_ptr) {
    int n = blockIdx.x * blockDim.x + threadIdx.x;
    if (n >= NROI) return;

    float stride_f = 16.0f;
    if (stride_ptr) {
        int iv = *(const int*)stride_ptr;
        stride_f = (iv > 0 && iv < 100000) ? (float)iv : *(const float*)stride_ptr;
    }
    const float sscale = 1.0f / stride_f;

    const float* r = rois + (size_t)n * 5;
    g_bidx[n] = (int)r[0];

    float rsw = __fmul_rn(rintf(r[1]), sscale);
    float rsh = __fmul_rn(rintf(r[2]), sscale);
    float rew = __fmul_rn(__fadd_rn(rintf(r[3]), 1.0f), sscale);
    float reh = __fmul_rn(__fadd_rn(rintf(r[4]), 1.0f), sscale);
    float rw  = __fsub_rn(rew, rsw);
    float rh  = __fsub_rn(reh, rsh);
    float rwm = __fmul_rn(rw, 1.3f);
    float rhm = __fmul_rn(rh, 1.3f);
    float swm = __fsub_rn(__fmul_rn(__fadd_rn(rsw, rew), 0.5f), __fmul_rn(rwm, 0.5f));
    float shm = __fsub_rn(__fmul_rn(__fadd_rn(rsh, reh), 0.5f), __fmul_rn(rhm, 0.5f));
    rwm = fmaxf(rwm, 0.1f);
    rhm = fmaxf(rhm, 0.1f);
    float bin_h = __fdiv_rn(rhm, 7.0f);
    float bin_w = __fdiv_rn(rwm, 7.0f);
    float dh = __fmul_rn(__fmul_rn(bin_h, 0.5f), 0.5f);   // bin_h*(1.5-1)*0.5
    float dw = __fmul_rn(__fmul_rn(bin_w, 0.5f), 0.5f);

    #pragma unroll
    for (int g = 0; g < GB; ++g) {
        float gf = (float)g;
        float hs_f = floorf(__fsub_rn(__fadd_rn(shm, __fmul_rn(gf, bin_h)), dh));
        float he_f = ceilf (__fadd_rn(__fadd_rn(shm, __fmul_rn(__fadd_rn(gf, 1.0f), bin_h)), dh));
        float ws_f = floorf(__fsub_rn(__fadd_rn(swm, __fmul_rn(gf, bin_w)), dw));
        float we_f = ceilf (__fadd_rn(__fadd_rn(swm, __fmul_rn(__fadd_rn(gf, 1.0f), bin_w)), dw));
        int hs = (int)fminf(fmaxf(hs_f, 0.0f), 128.0f);
        int he = (int)fminf(fmaxf(he_f, 0.0f), 128.0f);
        int ws = (int)fminf(fmaxf(ws_f, 0.0f), 128.0f);
        int we = (int)fminf(fmaxf(we_f, 0.0f), 128.0f);
        g_hb[n * GB + g] = (unsigned short)(hs | (he << 8));
        g_wb[n * GB + g] = (unsigned short)(ws | (we << 8));
    }
}

// ---------------- Kernel 2: fused integral + pool ----------------------------
// One CTA per (b,c) plane. Load plane (float4, coalesced) -> row scan with a
// single 5-step shfl scan of per-lane float4 sums -> column scan in smem ->
// pool all ROIs of batch b for this channel straight out of smem.
__global__ void k_fused(const float* __restrict__ feat,
                        float* __restrict__ out) {
    extern __shared__ float S[];          // [129][SST]

    const int bc   = blockIdx.x;          // 0 .. BB*CB-1
    const int b    = bc / CB;
    const int c    = bc % CB;
    const int tid  = threadIdx.x;         // 256 threads
    const int lane = tid & 31;
    const int warp = tid >> 5;            // 8 warps

    // --- zero pad row h==0 ---
    if (tid < SST) S[tid] = 0.0f;

    // --- row scan: warp per row, float4 per lane (full 512B row per LDG) ---
    const float* plane = feat + (size_t)bc * HB * WB;
    for (int h = warp; h < HB; h += 8) {
        const float4 v = reinterpret_cast<const float4*>(plane + h * WB)[lane];
        float s0 = v.x;
        float s1 = s0 + v.y;
        float s2 = s1 + v.z;
        float s3 = s2 + v.w;
        // inclusive warp scan of per-lane sums
        float sum = s3;
        #pragma unroll
        for (int o = 1; o < 32; o <<= 1) {
            float t = __shfl_up_sync(0xffffffffu, sum, o);
            if (lane >= o) sum += t;
        }
        float pre = sum - s3;             // exclusive prefix for this lane
        float* dst = S + (h + 1) * SST;
        if (lane == 0) dst[0] = 0.0f;     // pad column w==0
        dst[4 * lane + 1] = s0 + pre;
        dst[4 * lane + 2] = s1 + pre;
        dst[4 * lane + 3] = s2 + pre;
        dst[4 * lane + 4] = s3 + pre;
    }
    __syncthreads();

    // --- column scan: thread per column w=1..128 (conflict-free, SST=129) ---
    if (tid < HB) {
        const int w = tid + 1;
        float acc = 0.0f;
        #pragma unroll 8
        for (int h = 1; h <= HB; ++h) {
            acc += S[h * SST + w];
            S[h * SST + w] = acc;
        }
    }
    __syncthreads();

    // --- pool: table-driven, 4 smem reads + 1 div per (n) ---
    const int rem = c % (GB * GB);
    const int pi  = rem / GB;
    const int pj  = rem % GB;

    for (int n = tid; n < NROI; n += 256) {
        if (g_bidx[n] != b) continue;
        unsigned hb = g_hb[n * GB + pi];
        unsigned wb = g_wb[n * GB + pj];
        int hs = hb & 255, he = hb >> 8;
        int ws = wb & 255, we = wb >> 8;
        float tot = S[he * SST + we] - S[hs * SST + we]
                  - S[he * SST + ws] + S[hs * SST + ws];
        int area = (he - hs) * (we - ws);
        out[(size_t)n * CB + c] = (area > 0) ? __fdiv_rn(tot, (float)area) : 0.0f;
    }
}

// -----------------------------------------------------------------------------
extern "C" void kernel_launch(void* const* d_in, const int* in_sizes, int n_in,
                              void* d_out, int out_size) {
    // Identify inputs by element count (robust to ordering).
    const float* rois = nullptr;
    const float* feat = nullptr;
    const void*  stride_ptr = nullptr;
    for (int i = 0; i < n_in; ++i) {
        if (in_sizes[i] == NROI * 5)                  rois = (const float*)d_in[i];
        else if (in_sizes[i] == BB * CB * HB * WB)    feat = (const float*)d_in[i];
        else if (in_sizes[i] == 1)                    stride_ptr = d_in[i];
    }
    float* out = (float*)d_out;

    // >48 KB dynamic smem: opt in once (host-state change, capture-safe).
    static bool attr_set = false;
    if (!attr_set) {
        cudaFuncSetAttribute(k_fused,
                             cudaFuncAttributeMaxDynamicSharedMemorySize,
                             SMEM_BYTES);
        attr_set = true;
    }

    k_roi<<<2, 256>>>(rois, stride_ptr);
    k_fused<<<BB * CB, 256, SMEM_BYTES>>>(feat, out);
}

// round 16
// speedup vs baseline: 2.1064x; 1.1491x over previous
#include <cuda_runtime.h>
#include <cuda_bf16.h>
#include <math.h>

// ---------------- Problem constants (fixed by the dataset shapes) ------------
#define GB 7            // GROUP_SIZE
#define DB 10           // D = C / (G*G) = 490/49
#define BB 2            // batch
#define CB 490          // channels
#define HB 128          // feature H
#define WB 128          // feature W
#define NROI 512

// Smem integral image WITHOUT the zero pad row/col: S[h][w] (h,w in 0..127)
// holds I(h+1, w+1). Row stride 132 floats = 528 B = 16*33:
//   - every row base is 16B-aligned  -> cp.async.cg 16B and LDS.128 legal
//   - consecutive w -> consecutive banks -> conflict-free column & row access
#define SSTN 132
#define SMEM_BYTES (HB * SSTN * 4)        // 128*132*4 = 67584 B (dynamic smem)

// ---------------- Precomputed per-ROI bin table ------------------------------
// hs/he/ws/we in [0,128], packed (lo | hi<<8). Depends only on (n,g), not c.
__device__ int            g_bidx[NROI];
__device__ unsigned short g_hb[NROI * GB];   // hs | (he<<8), indexed [n*7+pi]
__device__ unsigned short g_wb[NROI * GB];   // ws | (we<<8), indexed [n*7+pj]

__device__ __forceinline__ unsigned smem_u32(const void* p) {
    unsigned a;
    asm("{ .reg .u64 t; cvta.to.shared.u64 t, %1; cvt.u32.u64 %0, t; }"
        : "=r"(a) : "l"(p));
    return a;
}

// ---------------- Kernel 1: ROI bin precompute (512 threads total) -----------
// Bin math mirrors the reference op-for-op; *_rn intrinsics forbid FMA
// contraction so floor/ceil boundaries match the JAX reference exactly.
__global__ void k_roi(const float* __restrict__ rois,
                      const void*  __restrict__ stride_ptr) {
    int n = blockIdx.x * blockDim.x + threadIdx.x;
    if (n >= NROI) return;

    float stride_f = 16.0f;
    if (stride_ptr) {
        int iv = *(const int*)stride_ptr;
        stride_f = (iv > 0 && iv < 100000) ? (float)iv : *(const float*)stride_ptr;
    }
    const float sscale = 1.0f / stride_f;

    const float* r = rois + (size_t)n * 5;
    g_bidx[n] = (int)r[0];

    float rsw = __fmul_rn(rintf(r[1]), sscale);
    float rsh = __fmul_rn(rintf(r[2]), sscale);
    float rew = __fmul_rn(__fadd_rn(rintf(r[3]), 1.0f), sscale);
    float reh = __fmul_rn(__fadd_rn(rintf(r[4]), 1.0f), sscale);
    float rw  = __fsub_rn(rew, rsw);
    float rh  = __fsub_rn(reh, rsh);
    float rwm = __fmul_rn(rw, 1.3f);
    float rhm = __fmul_rn(rh, 1.3f);
    float swm = __fsub_rn(__fmul_rn(__fadd_rn(rsw, rew), 0.5f), __fmul_rn(rwm, 0.5f));
    float shm = __fsub_rn(__fmul_rn(__fadd_rn(rsh, reh), 0.5f), __fmul_rn(rhm, 0.5f));
    rwm = fmaxf(rwm, 0.1f);
    rhm = fmaxf(rhm, 0.1f);
    float bin_h = __fdiv_rn(rhm, 7.0f);
    float bin_w = __fdiv_rn(rwm, 7.0f);
    float dh = __fmul_rn(__fmul_rn(bin_h, 0.5f), 0.5f);   // bin_h*(1.5-1)*0.5
    float dw = __fmul_rn(__fmul_rn(bin_w, 0.5f), 0.5f);

    #pragma unroll
    for (int g = 0; g < GB; ++g) {
        float gf = (float)g;
        float hs_f = floorf(__fsub_rn(__fadd_rn(shm, __fmul_rn(gf, bin_h)), dh));
        float he_f = ceilf (__fadd_rn(__fadd_rn(shm, __fmul_rn(__fadd_rn(gf, 1.0f), bin_h)), dh));
        float ws_f = floorf(__fsub_rn(__fadd_rn(swm, __fmul_rn(gf, bin_w)), dw));
        float we_f = ceilf (__fadd_rn(__fadd_rn(swm, __fmul_rn(__fadd_rn(gf, 1.0f), bin_w)), dw));
        int hs = (int)fminf(fmaxf(hs_f, 0.0f), 128.0f);
        int he = (int)fminf(fmaxf(he_f, 0.0f), 128.0f);
        int ws = (int)fminf(fmaxf(ws_f, 0.0f), 128.0f);
        int we = (int)fminf(fmaxf(we_f, 0.0f), 128.0f);
        g_hb[n * GB + g] = (unsigned short)(hs | (he << 8));
        g_wb[n * GB + g] = (unsigned short)(ws | (we << 8));
    }
}

// ---------------- Kernel 2: fused integral + pool ----------------------------
// One CTA per (b,c) plane.
//   1) cp.async the whole 64KB plane into smem (4096 independent 16B ops ->
//      fire-and-forget DRAM stream, latency fully hidden by MLP)
//   2) row scan in place (warp/row, float4 LDS + single shfl scan)
//   3) column scan split 2x64 + fixup (all 256 threads busy)
//   4) pool straight from smem using the precomputed bin table
__global__ void k_fused(const float* __restrict__ feat,
                        float* __restrict__ out) {
    extern __shared__ float S[];          // [128][SSTN]

    const int bc   = blockIdx.x;          // 0 .. BB*CB-1
    const int b    = bc / CB;
    const int c    = bc % CB;
    const int tid  = threadIdx.x;         // 256 threads
    const int lane = tid & 31;
    const int warp = tid >> 5;            // 8 warps

    // --- 1) async-stage the plane: chunk i -> row i>>5, 16B col (i&31) ---
    {
        const char* src = (const char*)(feat + (size_t)bc * HB * WB);
        unsigned sbase = smem_u32(S);
        #pragma unroll
        for (int k = 0; k < 16; ++k) {
            int i = tid + k * 256;                    // 0..4095
            unsigned dst = sbase + (unsigned)((i >> 5) * (SSTN * 4) + (i & 31) * 16);
            asm volatile("cp.async.cg.shared.global [%0], [%1], 16;"
                         :: "r"(dst), "l"(src + (size_t)i * 16) : "memory");
        }
        asm volatile("cp.async.commit_group;" ::: "memory");
        asm volatile("cp.async.wait_group 0;" ::: "memory");
    }
    __syncthreads();

    // --- 2) row-wise inclusive prefix, in place (warp per row) ---
    for (int h = warp; h < HB; h += 8) {
        float4* row = reinterpret_cast<float4*>(S + h * SSTN);
        float4 v = row[lane];
        float s0 = v.x;
        float s1 = s0 + v.y;
        float s2 = s1 + v.z;
        float s3 = s2 + v.w;
        float sum = s3;
        #pragma unroll
        for (int o = 1; o < 32; o <<= 1) {
            float t = __shfl_up_sync(0xffffffffu, sum, o);
            if (lane >= o) sum += t;
        }
        float pre = sum - s3;             // exclusive prefix for this lane
        v.x = s0 + pre; v.y = s1 + pre; v.z = s2 + pre; v.w = s3 + pre;
        row[lane] = v;
    }
    __syncthreads();

    // --- 3) column scan: 256 threads = 128 cols x 2 segments of 64 ---
    {
        const int w   = tid & 127;
        const int seg = tid >> 7;                 // 0 or 1
        float* col = S + seg * 64 * SSTN + w;
        float acc = 0.0f;
        #pragma unroll 8
        for (int h = 0; h < 64; ++h) {
            acc += col[h * SSTN];
            col[h * SSTN] = acc;
        }
    }
    __syncthreads();
    if (tid < HB) {                               // fixup: add seg-0 total to seg 1
        const int w = tid;
        float base = S[63 * SSTN + w];
        float* col = S + 64 * SSTN + w;
        #pragma unroll 8
        for (int h = 0; h < 64; ++h)
            col[h * SSTN] += base;
    }
    __syncthreads();

    // --- 4) pool: table lookups + predicated 4-corner reads ---
    const int rem = c % (GB * GB);
    const int pi  = rem / GB;
    const int pj  = rem % GB;

    for (int n = tid; n < NROI; n += 256) {
        if (g_bidx[n] != b) continue;
        unsigned hb = g_hb[n * GB + pi];
        unsigned wb = g_wb[n * GB + pj];
        int hs = hb & 255, he = (int)(hb >> 8);
        int ws = wb & 255, we = (int)(wb >> 8);
        int area = (he - hs) * (we - ws);
        float res = 0.0f;
        if (area > 0) {
            // S[h][w] = I(h+1, w+1); indices hs-1/ws-1 == -1 mean the exact-0 pad
            const float* Re = S + (he - 1) * SSTN;
            float tot = Re[we - 1];
            if (ws > 0)           tot -= Re[ws - 1];
            if (hs > 0) {
                const float* Rs = S + (hs - 1) * SSTN;
                tot -= Rs[we - 1];
                if (ws > 0)       tot += Rs[ws - 1];
            }
            res = __fdiv_rn(tot, (float)area);
        }
        out[(size_t)n * CB + c] = res;
    }
}

// -----------------------------------------------------------------------------
extern "C" void kernel_launch(void* const* d_in, const int* in_sizes, int n_in,
                              void* d_out, int out_size) {
    // Identify inputs by element count (robust to ordering).
    const float* rois = nullptr;
    const float* feat = nullptr;
    const void*  stride_ptr = nullptr;
    for (int i = 0; i < n_in; ++i) {
        if (in_sizes[i] == NROI * 5)                  rois = (const float*)d_in[i];
        else if (in_sizes[i] == BB * CB * HB * WB)    feat = (const float*)d_in[i];
        else if (in_sizes[i] == 1)                    stride_ptr = d_in[i];
    }
    float* out = (float*)d_out;

    // >48 KB dynamic smem: opt in once (host-state change, capture-safe).
    static bool attr_set = false;
    if (!attr_set) {
        cudaFuncSetAttribute(k_fused,
                             cudaFuncAttributeMaxDynamicSharedMemorySize,
                             SMEM_BYTES);
        attr_set = true;
    }

    k_roi<<<2, 256>>>(rois, stride_ptr);
    k_fused<<<BB * CB, 256, SMEM_BYTES>>>(feat, out);
}